// round 1
// baseline (speedup 1.0000x reference)
#include <cuda_runtime.h>

#define N_NODES 100000
#define D 128
#define TILE_M 128
#define ASTRIDE 132   // padded A-tile row stride (floats), 16B-aligned rows

// ---------------- scratch (no allocations allowed) ----------------
__device__ float g_H1[N_NODES * D];     // in@W1+b1
__device__ float g_T[N_NODES * D];      // relu(h)*norm_src  (message source)
__device__ float g_AGG[N_NODES * D];    // scatter-add target
__device__ float g_deg[2 * N_NODES];    // [outdeg | indeg]
__device__ float g_norm[2 * N_NODES];   // [nsrc | ndst]
__device__ float g_part[2 * 256 * D];   // column partial sums / sumsq
__device__ float g_bn[2 * D];           // folded BN: scale, shift

// ---------------- degrees ----------------
__global__ void k_degrees(const int* __restrict__ src, const int* __restrict__ dst, int E) {
    int e = blockIdx.x * blockDim.x + threadIdx.x;
    if (e < E) {
        atomicAdd(&g_deg[src[e]], 1.0f);              // exact (integer-valued)
        atomicAdd(&g_deg[N_NODES + dst[e]], 1.0f);
    }
}

__global__ void k_normdeg(int n) {
    int i = blockIdx.x * blockDim.x + threadIdx.x;
    if (i < n) {
        g_norm[i]           = rsqrtf(fmaxf(g_deg[i], 1.0f));
        g_norm[N_NODES + i] = rsqrtf(fmaxf(g_deg[N_NODES + i], 1.0f));
    }
}

// ---------------- BN column stats (deterministic two-stage) ----------------
__global__ void k_colstats(int M) {           // grid = 256 blocks x 256 threads
    int col  = threadIdx.x & 127;
    int roff = threadIdx.x >> 7;              // 0 or 1
    float s = 0.f, s2 = 0.f;
    for (int r = blockIdx.x * 2 + roff; r < M; r += gridDim.x * 2) {
        float v = g_H1[(long long)r * D + col];
        s += v; s2 += v * v;
    }
    __shared__ float sh[256], sh2[256];
    sh[threadIdx.x] = s; sh2[threadIdx.x] = s2;
    __syncthreads();
    if (roff == 0) {
        g_part[blockIdx.x * D + col]           = sh[col] + sh[128 + col];
        g_part[256 * D + blockIdx.x * D + col] = sh2[col] + sh2[128 + col];
    }
}

__global__ void k_finstats(const float* __restrict__ gamma, const float* __restrict__ beta, int M) {
    int c = threadIdx.x;  // 128 threads
    double s = 0.0, s2 = 0.0;
    for (int b = 0; b < 256; b++) {
        s  += (double)g_part[b * D + c];
        s2 += (double)g_part[256 * D + b * D + c];
    }
    float mu   = (float)(s / (double)M);
    float var  = (float)(s2 / (double)M) - mu * mu;
    float rstd = rsqrtf(var + 1e-5f);
    float sc   = gamma[c] * rstd;
    g_bn[c]     = sc;                 // x*sc + shift == gamma*(x-mu)*rstd + beta
    g_bn[D + c] = beta[c] - sc * mu;
}

// ---------------- edge scatter: AGG[dst] += T[src], vector atomics ----------------
__global__ void k_scatter(const int* __restrict__ src, const int* __restrict__ dst, int E) {
    int idx = blockIdx.x * blockDim.x + threadIdx.x;
    int e = idx >> 5;
    if (e >= E) return;
    int comp = idx & 31;                       // 32 float4 chunks per 128-float row
    int s = src[e], d = dst[e];                // broadcast within warp
    float4 v = ((const float4*)g_T)[(long long)s * 32 + comp];
    float4* p = ((float4*)g_AGG) + ((long long)d * 32 + comp);
    asm volatile("red.global.add.v4.f32 [%0], {%1,%2,%3,%4};"
                 :: "l"(p), "f"(v.x), "f"(v.y), "f"(v.z), "f"(v.w) : "memory");
}

// ---------------- fused GEMM: C[M,128] = op_A(A)[M,128] @ B[128,128], epilogue variants ----
// AOP: 0 = identity A load, 1 = BN(scale,shift)+ReLU applied to A load
// EPI: 0 = out = acc + bias
//      1 = out = relu(acc + bias) * nsrc[row]
//      2 = out = acc * ndst[row] + bias
//      3 = out = relu(acc * ndst[row] + bias) * nsrc[row]
template <int AOP, int EPI>
__global__ void __launch_bounds__(256) k_gemm(
    const float* __restrict__ A, const float* __restrict__ B,
    const float* __restrict__ bias, float* __restrict__ Out, int M)
{
    extern __shared__ float smem[];
    float* As = smem;                     // [128][ASTRIDE]
    float* Bs = smem + 128 * ASTRIDE;     // [128][128]
    int tid = threadIdx.x;
    int m0  = blockIdx.x * TILE_M;
    int rows = M - m0; if (rows > TILE_M) rows = TILE_M;

    // load B tile (full 128x128)
    const float4* B4 = (const float4*)B;
    #pragma unroll
    for (int idx = tid; idx < 128 * 32; idx += 256) {
        int r = idx >> 5, k4 = idx & 31;
        ((float4*)&Bs[r * D])[k4] = B4[r * 32 + k4];
    }
    // load A tile (with optional BN+ReLU)
    const float4* A4 = (const float4*)A;
    #pragma unroll
    for (int idx = tid; idx < 128 * 32; idx += 256) {
        int r = idx >> 5, k4 = idx & 31;
        float4 v = make_float4(0.f, 0.f, 0.f, 0.f);
        if (r < rows) v = A4[(long long)(m0 + r) * 32 + k4];
        if (AOP == 1) {
            float4 sc = ((const float4*)g_bn)[k4];
            float4 sh = ((const float4*)(g_bn + D))[k4];
            v.x = fmaxf(fmaf(v.x, sc.x, sh.x), 0.f);
            v.y = fmaxf(fmaf(v.y, sc.y, sh.y), 0.f);
            v.z = fmaxf(fmaf(v.z, sc.z, sh.z), 0.f);
            v.w = fmaxf(fmaf(v.w, sc.w, sh.w), 0.f);
        }
        *(float4*)&As[r * ASTRIDE + k4 * 4] = v;
    }
    __syncthreads();

    int tr = tid >> 4, tc = tid & 15;     // 16x16 thread grid, 8x8 microtile
    float acc[8][8];
    #pragma unroll
    for (int i = 0; i < 8; i++)
        #pragma unroll
        for (int j = 0; j < 8; j++) acc[i][j] = 0.f;

    #pragma unroll 4
    for (int k = 0; k < 128; k++) {
        float a[8];
        #pragma unroll
        for (int i = 0; i < 8; i++) a[i] = As[(tr * 8 + i) * ASTRIDE + k];
        float4 b0 = *(const float4*)&Bs[k * D + tc * 8];
        float4 b1 = *(const float4*)&Bs[k * D + tc * 8 + 4];
        float b[8] = {b0.x, b0.y, b0.z, b0.w, b1.x, b1.y, b1.z, b1.w};
        #pragma unroll
        for (int i = 0; i < 8; i++)
            #pragma unroll
            for (int j = 0; j < 8; j++)
                acc[i][j] = fmaf(a[i], b[j], acc[i][j]);
    }

    // epilogue
    int c0 = tc * 8;
    float4 bv0 = ((const float4*)bias)[c0 >> 2];
    float4 bv1 = ((const float4*)bias)[(c0 >> 2) + 1];
    float bb[8] = {bv0.x, bv0.y, bv0.z, bv0.w, bv1.x, bv1.y, bv1.z, bv1.w};
    #pragma unroll
    for (int i = 0; i < 8; i++) {
        int r = tr * 8 + i;
        if (r >= rows) continue;
        int row = m0 + r;
        float nd = 1.f, ns = 1.f;
        if (EPI >= 2) nd = g_norm[N_NODES + row];
        if (EPI == 1 || EPI == 3) ns = g_norm[row];
        float o[8];
        #pragma unroll
        for (int j = 0; j < 8; j++) {
            float x = (EPI >= 2) ? fmaf(acc[i][j], nd, bb[j]) : (acc[i][j] + bb[j]);
            if (EPI == 1 || EPI == 3) x = fmaxf(x, 0.f) * ns;
            o[j] = x;
        }
        float4* op = (float4*)&Out[(long long)row * D + c0];
        op[0] = make_float4(o[0], o[1], o[2], o[3]);
        op[1] = make_float4(o[4], o[5], o[6], o[7]);
    }
}

// ---------------- launch ----------------
extern "C" void kernel_launch(void* const* d_in, const int* in_sizes, int n_in,
                              void* d_out, int out_size)
{
    const float* in_feat = (const float*)d_in[0];
    const int*   src     = (const int*)d_in[1];
    const int*   dst     = (const int*)d_in[2];
    const float* W1 = (const float*)d_in[3];
    const float* b1 = (const float*)d_in[4];
    const float* gamma = (const float*)d_in[5];
    const float* beta  = (const float*)d_in[6];
    const float* W2 = (const float*)d_in[7];
    const float* b2 = (const float*)d_in[8];
    const float* Wc = (const float*)d_in[9];
    const float* bc = (const float*)d_in[10];
    float* out = (float*)d_out;

    int M = in_sizes[0] / D;   // 100000
    int E = in_sizes[1];       // 1600000

    const int SMEM_BYTES = (128 * ASTRIDE + 128 * D) * (int)sizeof(float);  // ~130 KB
    cudaFuncSetAttribute(k_gemm<0,0>, cudaFuncAttributeMaxDynamicSharedMemorySize, SMEM_BYTES);
    cudaFuncSetAttribute(k_gemm<1,1>, cudaFuncAttributeMaxDynamicSharedMemorySize, SMEM_BYTES);
    cudaFuncSetAttribute(k_gemm<0,3>, cudaFuncAttributeMaxDynamicSharedMemorySize, SMEM_BYTES);
    cudaFuncSetAttribute(k_gemm<0,2>, cudaFuncAttributeMaxDynamicSharedMemorySize, SMEM_BYTES);

    void *pH1, *pT, *pAGG, *pDeg;
    cudaGetSymbolAddress(&pH1,  g_H1);
    cudaGetSymbolAddress(&pT,   g_T);
    cudaGetSymbolAddress(&pAGG, g_AGG);
    cudaGetSymbolAddress(&pDeg, g_deg);

    int nblk = (M + TILE_M - 1) / TILE_M;

    // degrees + norms
    cudaMemsetAsync(pDeg, 0, 2 * N_NODES * sizeof(float));
    k_degrees<<<(E + 255) / 256, 256>>>(src, dst, E);
    k_normdeg<<<(N_NODES + 255) / 256, 256>>>(N_NODES);

    // H1 = in_feat @ W1 + b1
    k_gemm<0,0><<<nblk, 256, SMEM_BYTES>>>(in_feat, W1, b1, (float*)pH1, M);

    // BN stats (deterministic)
    k_colstats<<<256, 256>>>(M);
    k_finstats<<<1, 128>>>(gamma, beta, M);

    // T = relu( relu(BN(H1)) @ W2 + b2 ) * nsrc
    k_gemm<1,1><<<nblk, 256, SMEM_BYTES>>>((const float*)pH1, W2, b2, (float*)pT, M);

    // 3 propagation steps
    for (int step = 0; step < 3; step++) {
        cudaMemsetAsync(pAGG, 0, (size_t)M * D * sizeof(float));
        k_scatter<<<(E * 32 + 255) / 256, 256>>>(src, dst, E);
        if (step < 2)
            k_gemm<0,3><<<nblk, 256, SMEM_BYTES>>>((const float*)pAGG, Wc, bc, (float*)pT, M);
        else
            k_gemm<0,2><<<nblk, 256, SMEM_BYTES>>>((const float*)pAGG, Wc, bc, out, M);
    }
}